// round 15
// baseline (speedup 1.0000x reference)
#include <cuda_runtime.h>
#include <cuda_fp16.h>
#include <cstdint>
#include <math.h>

#define N_NODESK 50000
#define N_EDGESK 800000
#define F_INK    128
#define C1K      256     // HEADS*HID
#define HEADSK   8
#define NBLK_SCAN 196    // ceil(50000/256)
#define FULLMASK 0xffffffffu

// ---------------- scratch (device globals: allocation-free contract) ----------------
__device__ __half2 g_h1h[N_NODESK * 128];  // h1 in fp16 (half2 pairs), 25.6 MB
__device__ float g_as1[N_NODESK * HEADSK];
__device__ float g_ad1[N_NODESK * HEADSK];
__device__ float g_h2[N_NODESK * 2];
__device__ float g_as2[N_NODESK];
__device__ float g_ad2[N_NODESK];
__device__ int   g_cnt[N_NODESK];
__device__ int   g_rowptr[N_NODESK + 1];
__device__ int   g_cursor[N_NODESK];
__device__ int   g_col[N_EDGESK];          // src ids grouped by dst
__device__ int   g_bsum[NBLK_SCAN];

// ---------------- CSR build ----------------
__global__ void zero_cnt_kernel() {
    int i = blockIdx.x * blockDim.x + threadIdx.x;
    if (i < N_NODESK) g_cnt[i] = 0;
}

// 4 edges per thread, int4 loads -> 4 independent atomics (MLP=4)
__global__ void hist_kernel(const int* __restrict__ dst) {
    int t = blockIdx.x * blockDim.x + threadIdx.x;
    if (t < N_EDGESK / 4) {
        int4 d = ((const int4*)dst)[t];
        atomicAdd(&g_cnt[d.x], 1);
        atomicAdd(&g_cnt[d.y], 1);
        atomicAdd(&g_cnt[d.z], 1);
        atomicAdd(&g_cnt[d.w], 1);
    }
}

__global__ void blocksum_kernel() {
    int i = blockIdx.x * 256 + threadIdx.x;
    int v = (i < N_NODESK) ? g_cnt[i] : 0;
    __shared__ int ws[8];
    int lane = threadIdx.x & 31, w = threadIdx.x >> 5;
#pragma unroll
    for (int o = 16; o; o >>= 1) v += __shfl_xor_sync(FULLMASK, v, o);
    if (lane == 0) ws[w] = v;
    __syncthreads();
    if (threadIdx.x == 0) {
        int s = 0;
#pragma unroll
        for (int k = 0; k < 8; k++) s += ws[k];
        g_bsum[blockIdx.x] = s;
    }
}

// local scan, with the top-level prefix over g_bsum computed in-block (scantop fused away)
__global__ void scanlocal_kernel() {
    __shared__ int sh[256];
    __shared__ int wsum[8];
    // base = sum of g_bsum[0..blockIdx.x)
    int part = 0;
    for (int j = threadIdx.x; j < blockIdx.x; j += 256) part += g_bsum[j];
    {
        int lane = threadIdx.x & 31, w = threadIdx.x >> 5;
#pragma unroll
        for (int o = 16; o; o >>= 1) part += __shfl_xor_sync(FULLMASK, part, o);
        if (lane == 0) wsum[w] = part;
    }
    __syncthreads();
    int base = wsum[0] + wsum[1] + wsum[2] + wsum[3] + wsum[4] + wsum[5] + wsum[6] + wsum[7];

    int i = blockIdx.x * 256 + threadIdx.x;
    int v = (i < N_NODESK) ? g_cnt[i] : 0;
    sh[threadIdx.x] = v;
    __syncthreads();
    for (int off = 1; off < 256; off <<= 1) {
        int t = (threadIdx.x >= off) ? sh[threadIdx.x - off] : 0;
        __syncthreads();
        sh[threadIdx.x] += t;
        __syncthreads();
    }
    int incl = sh[threadIdx.x];
    if (i < N_NODESK) {
        int excl = base + incl - v;
        g_rowptr[i] = excl;
        g_cursor[i] = excl;
        if (i == N_NODESK - 1) g_rowptr[N_NODESK] = base + incl;
    }
}

// 4 edges per thread, int4 loads, independent atomics
__global__ void scatter_kernel(const int* __restrict__ src, const int* __restrict__ dst) {
    int t = blockIdx.x * blockDim.x + threadIdx.x;
    if (t < N_EDGESK / 4) {
        int4 s = ((const int4*)src)[t];
        int4 d = ((const int4*)dst)[t];
        int p0 = atomicAdd(&g_cursor[d.x], 1);
        int p1 = atomicAdd(&g_cursor[d.y], 1);
        int p2 = atomicAdd(&g_cursor[d.z], 1);
        int p3 = atomicAdd(&g_cursor[d.w], 1);
        g_col[p0] = s.x;
        g_col[p1] = s.y;
        g_col[p2] = s.z;
        g_col[p3] = s.w;
    }
}

// ---------------- tensor-core SGEMM (3xTF32) + fused alpha1, fp16 h1 output ----------
__device__ __forceinline__ void tf32_split(float v, unsigned int& hi, unsigned int& lo) {
    asm("cvt.rna.tf32.f32 %0, %1;" : "=r"(hi) : "f"(v));
    float r = v - __uint_as_float(hi);
    asm("cvt.rna.tf32.f32 %0, %1;" : "=r"(lo) : "f"(r));
}

__device__ __forceinline__ void mma_tf32(float* c, const unsigned int* a, const unsigned int* b) {
    asm volatile(
        "mma.sync.aligned.m16n8k8.row.col.f32.tf32.tf32.f32 "
        "{%0,%1,%2,%3}, {%4,%5,%6,%7}, {%8,%9}, {%0,%1,%2,%3};"
        : "+f"(c[0]), "+f"(c[1]), "+f"(c[2]), "+f"(c[3])
        : "r"(a[0]), "r"(a[1]), "r"(a[2]), "r"(a[3]), "r"(b[0]), "r"(b[1]));
}

__global__ __launch_bounds__(256, 2) void sgemm_tc_kernel(const float* __restrict__ A,
                                                          const float* __restrict__ B,
                                                          const float* __restrict__ a1s,
                                                          const float* __restrict__ a1d) {
    __shared__ unsigned int sAh[128][20], sAl[128][20];   // [m][k] k-minor, pad->20
    __shared__ unsigned int sBh[16][72],  sBl[16][72];    // [k][n] n-minor, pad->72

    const int tid  = threadIdx.x;
    const int lane = tid & 31;
    const int wid  = tid >> 5;
    const int g    = lane >> 2;       // 0..7
    const int tg   = lane & 3;        // 0..3
    const int m0   = (wid & 3) * 32;
    const int n0   = (wid >> 2) * 32;
    const int bm   = blockIdx.y * 128;
    const int bn   = blockIdx.x * 64;

    float c[2][4][4];
#pragma unroll
    for (int mi = 0; mi < 2; mi++)
#pragma unroll
        for (int ni = 0; ni < 4; ni++)
#pragma unroll
            for (int q = 0; q < 4; q++) c[mi][ni][q] = 0.f;

    for (int kt = 0; kt < F_INK; kt += 16) {
#pragma unroll
        for (int i = 0; i < 2; i++) {
            int idx = tid + i * 256;
            int row = idx >> 2, kq = idx & 3;
            float4 v = make_float4(0.f, 0.f, 0.f, 0.f);
            int grow = bm + row;
            if (grow < N_NODESK)
                v = *(const float4*)(A + (size_t)grow * F_INK + kt + kq * 4);
            uint4 h, l;
            tf32_split(v.x, h.x, l.x);
            tf32_split(v.y, h.y, l.y);
            tf32_split(v.z, h.z, l.z);
            tf32_split(v.w, h.w, l.w);
            *(uint4*)&sAh[row][kq * 4] = h;
            *(uint4*)&sAl[row][kq * 4] = l;
        }
        {
            int k = tid >> 4, cq = tid & 15;
            float4 v = *(const float4*)(B + (size_t)(kt + k) * C1K + bn + cq * 4);
            uint4 h, l;
            tf32_split(v.x, h.x, l.x);
            tf32_split(v.y, h.y, l.y);
            tf32_split(v.z, h.z, l.z);
            tf32_split(v.w, h.w, l.w);
            *(uint4*)&sBh[k][cq * 4] = h;
            *(uint4*)&sBl[k][cq * 4] = l;
        }
        __syncthreads();
#pragma unroll
        for (int k0 = 0; k0 < 16; k0 += 8) {
            unsigned int ah[2][4], al[2][4], bh[4][2], bl[4][2];
#pragma unroll
            for (int mi = 0; mi < 2; mi++) {
                int r = m0 + mi * 16;
                ah[mi][0] = sAh[r + g][k0 + tg];
                ah[mi][1] = sAh[r + 8 + g][k0 + tg];
                ah[mi][2] = sAh[r + g][k0 + tg + 4];
                ah[mi][3] = sAh[r + 8 + g][k0 + tg + 4];
                al[mi][0] = sAl[r + g][k0 + tg];
                al[mi][1] = sAl[r + 8 + g][k0 + tg];
                al[mi][2] = sAl[r + g][k0 + tg + 4];
                al[mi][3] = sAl[r + 8 + g][k0 + tg + 4];
            }
#pragma unroll
            for (int ni = 0; ni < 4; ni++) {
                int col = n0 + ni * 8 + g;
                bh[ni][0] = sBh[k0 + tg][col];
                bh[ni][1] = sBh[k0 + tg + 4][col];
                bl[ni][0] = sBl[k0 + tg][col];
                bl[ni][1] = sBl[k0 + tg + 4][col];
            }
#pragma unroll
            for (int mi = 0; mi < 2; mi++)
#pragma unroll
                for (int ni = 0; ni < 4; ni++) {
                    mma_tf32(c[mi][ni], ah[mi], bh[ni]);
                    mma_tf32(c[mi][ni], ah[mi], bl[ni]);
                    mma_tf32(c[mi][ni], al[mi], bh[ni]);
                }
        }
        __syncthreads();
    }

    // store C tile as fp16 (half2 per channel pair)
#pragma unroll
    for (int mi = 0; mi < 2; mi++)
#pragma unroll
        for (int ni = 0; ni < 4; ni++) {
            int r = bm + m0 + mi * 16 + g;
            int col = bn + n0 + ni * 8 + tg * 2;   // even
            if (r < N_NODESK)
                g_h1h[(size_t)r * 128 + (col >> 1)] =
                    __floats2half2_rn(c[mi][ni][0], c[mi][ni][1]);
            if (r + 8 < N_NODESK)
                g_h1h[(size_t)(r + 8) * 128 + (col >> 1)] =
                    __floats2half2_rn(c[mi][ni][2], c[mi][ni][3]);
        }

    // fused alpha1 from fp32 accumulators: this warp's 32-col slab == one head
    {
        int hidx = (bn >> 5) + (wid >> 2);
        float s[4] = {0.f, 0.f, 0.f, 0.f};
        float d[4] = {0.f, 0.f, 0.f, 0.f};
#pragma unroll
        for (int ni = 0; ni < 4; ni++) {
            int lc = ni * 8 + tg * 2;
            float as0 = a1s[hidx * 32 + lc], as1 = a1s[hidx * 32 + lc + 1];
            float ad0 = a1d[hidx * 32 + lc], ad1 = a1d[hidx * 32 + lc + 1];
            s[0] += c[0][ni][0] * as0 + c[0][ni][1] * as1;
            s[1] += c[0][ni][2] * as0 + c[0][ni][3] * as1;
            s[2] += c[1][ni][0] * as0 + c[1][ni][1] * as1;
            s[3] += c[1][ni][2] * as0 + c[1][ni][3] * as1;
            d[0] += c[0][ni][0] * ad0 + c[0][ni][1] * ad1;
            d[1] += c[0][ni][2] * ad0 + c[0][ni][3] * ad1;
            d[2] += c[1][ni][0] * ad0 + c[1][ni][1] * ad1;
            d[3] += c[1][ni][2] * ad0 + c[1][ni][3] * ad1;
        }
#pragma unroll
        for (int off = 1; off <= 2; off <<= 1) {
#pragma unroll
            for (int j = 0; j < 4; j++) {
                s[j] += __shfl_xor_sync(FULLMASK, s[j], off);
                d[j] += __shfl_xor_sync(FULLMASK, d[j], off);
            }
        }
        if (tg == 0) {
            int rbase = bm + m0 + g;
#pragma unroll
            for (int j = 0; j < 4; j++) {
                int r = rbase + ((j & 1) ? 8 : 0) + ((j >> 1) ? 16 : 0);
                if (r < N_NODESK) {
                    g_as1[r * 8 + hidx] = s[j];
                    g_ad1[r * 8 + hidx] = d[j];
                }
            }
        }
    }
}

__device__ __forceinline__ float lrelu02(float x) { return x > 0.f ? x : 0.2f * x; }
__device__ __forceinline__ float eluf(float x)    { return x > 0.f ? x : expm1f(x); }

// accumulate 4 fp16 channels (one uint2 = 2 half2) into fp32 acc with weight w
__device__ __forceinline__ void acc_h4(float4& acc, uint2 p, float w) {
    float2 a = __half22float2(*(__half2*)&p.x);
    float2 b = __half22float2(*(__half2*)&p.y);
    acc.x += w * a.x; acc.y += w * a.y;
    acc.z += w * b.x; acc.w += w * b.y;
}

// ---------------- layer-1 aggregation (pipelined quad-edge, fp16 gather) + layer-2 fuse --
__global__ __launch_bounds__(256) void agg1_kernel(const float* __restrict__ b1,
                                                   const float* __restrict__ W2,
                                                   const float* __restrict__ a2s,
                                                   const float* __restrict__ a2d) {
    int warp = (blockIdx.x * blockDim.x + threadIdx.x) >> 5;
    int lane = threadIdx.x & 31;
    if (warp >= N_NODESK) return;
    const int n = warp;
    const int hA = lane >> 3;
    const int hB = 4 + hA;
    const int l7 = lane & 7;
    const int grp = lane >> 3;
    const float ad8 = g_ad1[n * 8 + l7];

    float4 accA = make_float4(0.f, 0.f, 0.f, 0.f);
    float4 accB = make_float4(0.f, 0.f, 0.f, 0.f);
    float denA = 0.f, denB = 0.f;

    const int beg = g_rowptr[n], end = g_rowptr[n + 1];

    {   // self loop
        float w = __expf(lrelu02(g_as1[n * 8 + l7] + ad8));
        float wA = __shfl_sync(FULLMASK, w, hA);
        float wB = __shfl_sync(FULLMASK, w, hB);
        const uint2* row = (const uint2*)(g_h1h + (size_t)n * 128);
        acc_h4(accA, row[lane], wA);
        acc_h4(accB, row[32 + lane], wB);
        denA += wA; denB += wB;
    }

    // software-pipelined quad loop: next quad's col/logit/exp issued before
    // the current quad's 8 gathers + FMAs, hiding the dependent chain.
    int e = beg;
    int ss = 0; float w = 0.f;
    bool have = (e + 4 <= end);
    if (have) {
        ss = g_col[e + grp];
        w = __expf(lrelu02(g_as1[ss * 8 + l7] + ad8));
    }
    while (have) {
        int en = e + 4;
        bool hn = (en + 4 <= end);
        int ssn = 0; float wn = 0.f;
        if (hn) {
            ssn = g_col[en + grp];
            wn = __expf(lrelu02(g_as1[ssn * 8 + l7] + ad8));
        }
#pragma unroll
        for (int j = 0; j < 4; ++j) {
            int  sj = __shfl_sync(FULLMASK, ss, j * 8);
            float wA = __shfl_sync(FULLMASK, w, j * 8 + hA);
            float wB = __shfl_sync(FULLMASK, w, j * 8 + hB);
            const uint2* row = (const uint2*)(g_h1h + (size_t)sj * 128);
            acc_h4(accA, row[lane], wA);
            acc_h4(accB, row[32 + lane], wB);
            denA += wA; denB += wB;
        }
        e = en; ss = ssn; w = wn; have = hn;
    }
    for (; e < end; ++e) {
        int s = g_col[e];
        float w1 = __expf(lrelu02(g_as1[s * 8 + l7] + ad8));
        float wA = __shfl_sync(FULLMASK, w1, hA);
        float wB = __shfl_sync(FULLMASK, w1, hB);
        const uint2* row = (const uint2*)(g_h1h + (size_t)s * 128);
        acc_h4(accA, row[lane], wA);
        acc_h4(accB, row[32 + lane], wB);
        denA += wA; denB += wB;
    }

    float rA = 1.f / denA, rB = 1.f / denB;
    const float4 bA = *(const float4*)(b1 + 4 * lane);
    const float4 bB = *(const float4*)(b1 + 128 + 4 * lane);
    float4 oA, oB;
    oA.x = eluf(accA.x * rA + bA.x); oA.y = eluf(accA.y * rA + bA.y);
    oA.z = eluf(accA.z * rA + bA.z); oA.w = eluf(accA.w * rA + bA.w);
    oB.x = eluf(accB.x * rB + bB.x); oB.y = eluf(accB.y * rB + bB.y);
    oB.z = eluf(accB.z * rB + bB.z); oB.w = eluf(accB.w * rB + bB.w);

    int cA = 4 * lane, cB = 128 + 4 * lane;
    float acc0 = oA.x * W2[(cA + 0) * 2] + oA.y * W2[(cA + 1) * 2]
               + oA.z * W2[(cA + 2) * 2] + oA.w * W2[(cA + 3) * 2]
               + oB.x * W2[(cB + 0) * 2] + oB.y * W2[(cB + 1) * 2]
               + oB.z * W2[(cB + 2) * 2] + oB.w * W2[(cB + 3) * 2];
    float acc1 = oA.x * W2[(cA + 0) * 2 + 1] + oA.y * W2[(cA + 1) * 2 + 1]
               + oA.z * W2[(cA + 2) * 2 + 1] + oA.w * W2[(cA + 3) * 2 + 1]
               + oB.x * W2[(cB + 0) * 2 + 1] + oB.y * W2[(cB + 1) * 2 + 1]
               + oB.z * W2[(cB + 2) * 2 + 1] + oB.w * W2[(cB + 3) * 2 + 1];
#pragma unroll
    for (int o = 16; o; o >>= 1) {
        acc0 += __shfl_xor_sync(FULLMASK, acc0, o);
        acc1 += __shfl_xor_sync(FULLMASK, acc1, o);
    }
    if (lane == 0) {
        g_h2[n * 2 + 0] = acc0;
        g_h2[n * 2 + 1] = acc1;
        g_as2[n] = acc0 * a2s[0] + acc1 * a2s[1];
        g_ad2[n] = acc0 * a2d[0] + acc1 * a2d[1];
    }
}

// ---------------- layer-2 aggregation: warp per dst node (edge-parallel) ----------------
__global__ __launch_bounds__(256) void agg2_kernel(const float* __restrict__ b2,
                                                   float* __restrict__ out) {
    int warp = (blockIdx.x * blockDim.x + threadIdx.x) >> 5;
    int lane = threadIdx.x & 31;
    if (warp >= N_NODESK) return;
    const int n = warp;
    float adn = g_ad2[n];
    int beg = g_rowptr[n], end = g_rowptr[n + 1];
    float den = 0.f, o0 = 0.f, o1 = 0.f;
    for (int e = beg + lane; e < end; e += 32) {
        int s = g_col[e];
        float w = __expf(lrelu02(g_as2[s] + adn));
        den += w;
        o0 += w * g_h2[s * 2 + 0];
        o1 += w * g_h2[s * 2 + 1];
    }
    if (lane == 0) {
        float w = __expf(lrelu02(g_as2[n] + adn));
        den += w;
        o0 += w * g_h2[n * 2 + 0];
        o1 += w * g_h2[n * 2 + 1];
    }
#pragma unroll
    for (int o = 16; o; o >>= 1) {
        den += __shfl_xor_sync(FULLMASK, den, o);
        o0  += __shfl_xor_sync(FULLMASK, o0, o);
        o1  += __shfl_xor_sync(FULLMASK, o1, o);
    }
    if (lane == 0) {
        float r = 1.f / den;
        out[n * 2 + 0] = o0 * r + b2[0];
        out[n * 2 + 1] = o1 * r + b2[1];
    }
}

// ---------------- launch ----------------
extern "C" void kernel_launch(void* const* d_in, const int* in_sizes, int n_in,
                              void* d_out, int out_size) {
    const float* x    = (const float*)d_in[0];
    const int*   ei   = (const int*)d_in[1];
    const float* W1   = (const float*)d_in[3];
    const float* a1s  = (const float*)d_in[4];
    const float* a1d  = (const float*)d_in[5];
    const float* b1   = (const float*)d_in[6];
    const float* W2   = (const float*)d_in[7];
    const float* a2s  = (const float*)d_in[8];
    const float* a2d  = (const float*)d_in[9];
    const float* b2   = (const float*)d_in[10];
    float* out = (float*)d_out;

    const int* src = ei;
    const int* dst = ei + N_EDGESK;

    zero_cnt_kernel<<<(N_NODESK + 255) / 256, 256>>>();
    hist_kernel<<<(N_EDGESK / 4 + 255) / 256, 256>>>(dst);
    blocksum_kernel<<<NBLK_SCAN, 256>>>();
    sgemm_tc_kernel<<<dim3(C1K / 64, (N_NODESK + 127) / 128), 256>>>(x, W1, a1s, a1d);
    scanlocal_kernel<<<NBLK_SCAN, 256>>>();
    scatter_kernel<<<(N_EDGESK / 4 + 255) / 256, 256>>>(src, dst);

    agg1_kernel<<<(N_NODESK * 32 + 255) / 256, 256>>>(b1, W2, a2s, a2d);
    agg2_kernel<<<(N_NODESK * 32 + 255) / 256, 256>>>(b2, out);
}

// round 16
// speedup vs baseline: 1.1693x; 1.1693x over previous
#include <cuda_runtime.h>
#include <cuda_fp16.h>
#include <cstdint>
#include <math.h>

#define N_NODESK 50000
#define N_EDGESK 800000
#define F_INK    128
#define C1K      256     // HEADS*HID
#define HEADSK   8
#define NBLK_SCAN 196    // ceil(50000/256)
#define FULLMASK 0xffffffffu

// ---------------- scratch (device globals: allocation-free contract) ----------------
__device__ __half2 g_h1h[N_NODESK * 128];  // h1 in fp16 (half2 pairs), 25.6 MB
__device__ __half  g_W1th[C1K * F_INK];    // W1^T hi-half, [n][k]
__device__ __half  g_W1tl[C1K * F_INK];    // W1^T lo-half, [n][k]
__device__ float g_as1[N_NODESK * HEADSK];
__device__ float g_ad1[N_NODESK * HEADSK];
__device__ float g_h2[N_NODESK * 2];
__device__ float g_as2[N_NODESK];
__device__ float g_ad2[N_NODESK];
__device__ int   g_cnt[N_NODESK];
__device__ int   g_rowptr[N_NODESK + 1];
__device__ int   g_cursor[N_NODESK];
__device__ int   g_col[N_EDGESK];          // src ids grouped by dst
__device__ int   g_bsum[NBLK_SCAN];

// ---------------- CSR build ----------------
__global__ void zero_cnt_kernel() {
    int i = blockIdx.x * blockDim.x + threadIdx.x;
    if (i < N_NODESK) g_cnt[i] = 0;
}

// one-time W1 transpose + fp16 hi/lo split: g_W1t*[n][k]
__global__ void splitW1_kernel(const float* __restrict__ W1) {
    int t = blockIdx.x * blockDim.x + threadIdx.x;
    if (t < F_INK * C1K) {
        int k = t & (F_INK - 1);
        int n = t >> 7;
        float v = W1[(size_t)k * C1K + n];
        __half h = __float2half_rn(v);
        float l = v - __half2float(h);
        g_W1th[n * F_INK + k] = h;
        g_W1tl[n * F_INK + k] = __float2half_rn(l);
    }
}

// 4 edges per thread, int4 loads -> 4 independent atomics (MLP=4)
__global__ void hist_kernel(const int* __restrict__ dst) {
    int t = blockIdx.x * blockDim.x + threadIdx.x;
    if (t < N_EDGESK / 4) {
        int4 d = ((const int4*)dst)[t];
        atomicAdd(&g_cnt[d.x], 1);
        atomicAdd(&g_cnt[d.y], 1);
        atomicAdd(&g_cnt[d.z], 1);
        atomicAdd(&g_cnt[d.w], 1);
    }
}

__global__ void blocksum_kernel() {
    int i = blockIdx.x * 256 + threadIdx.x;
    int v = (i < N_NODESK) ? g_cnt[i] : 0;
    __shared__ int ws[8];
    int lane = threadIdx.x & 31, w = threadIdx.x >> 5;
#pragma unroll
    for (int o = 16; o; o >>= 1) v += __shfl_xor_sync(FULLMASK, v, o);
    if (lane == 0) ws[w] = v;
    __syncthreads();
    if (threadIdx.x == 0) {
        int s = 0;
#pragma unroll
        for (int k = 0; k < 8; k++) s += ws[k];
        g_bsum[blockIdx.x] = s;
    }
}

// local scan with top-level prefix over g_bsum computed in-block
__global__ void scanlocal_kernel() {
    __shared__ int sh[256];
    __shared__ int wsum[8];
    int part = 0;
    for (int j = threadIdx.x; j < blockIdx.x; j += 256) part += g_bsum[j];
    {
        int lane = threadIdx.x & 31, w = threadIdx.x >> 5;
#pragma unroll
        for (int o = 16; o; o >>= 1) part += __shfl_xor_sync(FULLMASK, part, o);
        if (lane == 0) wsum[w] = part;
    }
    __syncthreads();
    int base = wsum[0] + wsum[1] + wsum[2] + wsum[3] + wsum[4] + wsum[5] + wsum[6] + wsum[7];

    int i = blockIdx.x * 256 + threadIdx.x;
    int v = (i < N_NODESK) ? g_cnt[i] : 0;
    sh[threadIdx.x] = v;
    __syncthreads();
    for (int off = 1; off < 256; off <<= 1) {
        int t = (threadIdx.x >= off) ? sh[threadIdx.x - off] : 0;
        __syncthreads();
        sh[threadIdx.x] += t;
        __syncthreads();
    }
    int incl = sh[threadIdx.x];
    if (i < N_NODESK) {
        int excl = base + incl - v;
        g_rowptr[i] = excl;
        g_cursor[i] = excl;
        if (i == N_NODESK - 1) g_rowptr[N_NODESK] = base + incl;
    }
}

__global__ void scatter_kernel(const int* __restrict__ src, const int* __restrict__ dst) {
    int t = blockIdx.x * blockDim.x + threadIdx.x;
    if (t < N_EDGESK / 4) {
        int4 s = ((const int4*)src)[t];
        int4 d = ((const int4*)dst)[t];
        int p0 = atomicAdd(&g_cursor[d.x], 1);
        int p1 = atomicAdd(&g_cursor[d.y], 1);
        int p2 = atomicAdd(&g_cursor[d.z], 1);
        int p3 = atomicAdd(&g_cursor[d.w], 1);
        g_col[p0] = s.x;
        g_col[p1] = s.y;
        g_col[p2] = s.z;
        g_col[p3] = s.w;
    }
}

// ---------------- tensor-core SGEMM (3-term fp16-split) + fused alpha1 ----------------
// h1 = x @ W1 computed as Ah*Bh + Ah*Bl + Al*Bh with fp16 mma (exact 11x11-bit products,
// fp32 accumulate; dropped Al*Bl ~ 2.4e-7 rel). CTA tile 128m x 64n, warp tile 32x32,
// K-stage 32 (4 stages). C fragment layout identical to tf32 variant.

__device__ __forceinline__ void h2split(float a, float b, unsigned int& hi, unsigned int& lo) {
    __half ha = __float2half_rn(a), hb = __float2half_rn(b);
    __half la = __float2half_rn(a - __half2float(ha));
    __half lb = __float2half_rn(b - __half2float(hb));
    hi = ((unsigned int)__half_as_ushort(hb) << 16) | __half_as_ushort(ha);
    lo = ((unsigned int)__half_as_ushort(lb) << 16) | __half_as_ushort(la);
}

__device__ __forceinline__ void mma_f16(float* c, const unsigned int* a, const unsigned int* b) {
    asm volatile(
        "mma.sync.aligned.m16n8k16.row.col.f32.f16.f16.f32 "
        "{%0,%1,%2,%3}, {%4,%5,%6,%7}, {%8,%9}, {%0,%1,%2,%3};"
        : "+f"(c[0]), "+f"(c[1]), "+f"(c[2]), "+f"(c[3])
        : "r"(a[0]), "r"(a[1]), "r"(a[2]), "r"(a[3]), "r"(b[0]), "r"(b[1]));
}

__global__ __launch_bounds__(256, 2) void sgemm_tc_kernel(const float* __restrict__ A,
                                                          const float* __restrict__ a1s,
                                                          const float* __restrict__ a1d) {
    // payload: 16 half2 (=32 k) per row; stride 20 words for conflict-free frags
    __shared__ unsigned int sAh[128][20], sAl[128][20];
    __shared__ unsigned int sBh[64][20],  sBl[64][20];

    const int tid  = threadIdx.x;
    const int lane = tid & 31;
    const int wid  = tid >> 5;
    const int g    = lane >> 2;       // 0..7
    const int tg   = lane & 3;        // 0..3
    const int m0   = (wid & 3) * 32;
    const int n0   = (wid >> 2) * 32;
    const int bm   = blockIdx.y * 128;
    const int bn   = blockIdx.x * 64;

    float c[2][4][4];
#pragma unroll
    for (int mi = 0; mi < 2; mi++)
#pragma unroll
        for (int ni = 0; ni < 4; ni++)
#pragma unroll
            for (int q = 0; q < 4; q++) c[mi][ni][q] = 0.f;

    for (int kt = 0; kt < F_INK; kt += 32) {
        // A tile: 128 rows x 32 k floats = 1024 float4; 4 per thread; split to fp16 hi/lo
#pragma unroll
        for (int i = 0; i < 4; i++) {
            int idx = tid + i * 256;
            int row = idx >> 3, kq = idx & 7;
            float4 v = make_float4(0.f, 0.f, 0.f, 0.f);
            int grow = bm + row;
            if (grow < N_NODESK)
                v = *(const float4*)(A + (size_t)grow * F_INK + kt + kq * 4);
            unsigned int h0, l0, h1, l1;
            h2split(v.x, v.y, h0, l0);
            h2split(v.z, v.w, h1, l1);
            sAh[row][kq * 2 + 0] = h0;
            sAh[row][kq * 2 + 1] = h1;
            sAl[row][kq * 2 + 0] = l0;
            sAl[row][kq * 2 + 1] = l1;
        }
        // B tile from pre-split W1^T [n][k] halves: 64 rows x 32 k; uint4 = 8 halves/thread
        {
            int row = tid >> 2, kq = tid & 3;
            const uint4 vh = *(const uint4*)(g_W1th + (size_t)(bn + row) * F_INK + kt + kq * 8);
            const uint4 vl = *(const uint4*)(g_W1tl + (size_t)(bn + row) * F_INK + kt + kq * 8);
            sBh[row][kq * 4 + 0] = vh.x; sBh[row][kq * 4 + 1] = vh.y;
            sBh[row][kq * 4 + 2] = vh.z; sBh[row][kq * 4 + 3] = vh.w;
            sBl[row][kq * 4 + 0] = vl.x; sBl[row][kq * 4 + 1] = vl.y;
            sBl[row][kq * 4 + 2] = vl.z; sBl[row][kq * 4 + 3] = vl.w;
        }
        __syncthreads();
#pragma unroll
        for (int s = 0; s < 2; ++s) {        // two k16 steps per stage
            const int kk = s * 8;
            unsigned int ah[2][4], al[2][4], bh[4][2], bl[4][2];
#pragma unroll
            for (int mi = 0; mi < 2; mi++) {
                int r = m0 + mi * 16;
                ah[mi][0] = sAh[r + g][kk + tg];
                ah[mi][1] = sAh[r + 8 + g][kk + tg];
                ah[mi][2] = sAh[r + g][kk + tg + 4];
                ah[mi][3] = sAh[r + 8 + g][kk + tg + 4];
                al[mi][0] = sAl[r + g][kk + tg];
                al[mi][1] = sAl[r + 8 + g][kk + tg];
                al[mi][2] = sAl[r + g][kk + tg + 4];
                al[mi][3] = sAl[r + 8 + g][kk + tg + 4];
            }
#pragma unroll
            for (int ni = 0; ni < 4; ni++) {
                int col = n0 + ni * 8 + g;
                bh[ni][0] = sBh[col][kk + tg];
                bh[ni][1] = sBh[col][kk + tg + 4];
                bl[ni][0] = sBl[col][kk + tg];
                bl[ni][1] = sBl[col][kk + tg + 4];
            }
#pragma unroll
            for (int mi = 0; mi < 2; mi++)
#pragma unroll
                for (int ni = 0; ni < 4; ni++) {
                    mma_f16(c[mi][ni], ah[mi], bh[ni]);
                    mma_f16(c[mi][ni], ah[mi], bl[ni]);
                    mma_f16(c[mi][ni], al[mi], bh[ni]);
                }
        }
        __syncthreads();
    }

    // store C tile as fp16 (half2 per channel pair)
#pragma unroll
    for (int mi = 0; mi < 2; mi++)
#pragma unroll
        for (int ni = 0; ni < 4; ni++) {
            int r = bm + m0 + mi * 16 + g;
            int col = bn + n0 + ni * 8 + tg * 2;   // even
            if (r < N_NODESK)
                g_h1h[(size_t)r * 128 + (col >> 1)] =
                    __floats2half2_rn(c[mi][ni][0], c[mi][ni][1]);
            if (r + 8 < N_NODESK)
                g_h1h[(size_t)(r + 8) * 128 + (col >> 1)] =
                    __floats2half2_rn(c[mi][ni][2], c[mi][ni][3]);
        }

    // fused alpha1 from fp32 accumulators: this warp's 32-col slab == one head
    {
        int hidx = (bn >> 5) + (wid >> 2);
        float s[4] = {0.f, 0.f, 0.f, 0.f};
        float d[4] = {0.f, 0.f, 0.f, 0.f};
#pragma unroll
        for (int ni = 0; ni < 4; ni++) {
            int lc = ni * 8 + tg * 2;
            float as0 = a1s[hidx * 32 + lc], as1 = a1s[hidx * 32 + lc + 1];
            float ad0 = a1d[hidx * 32 + lc], ad1 = a1d[hidx * 32 + lc + 1];
            s[0] += c[0][ni][0] * as0 + c[0][ni][1] * as1;
            s[1] += c[0][ni][2] * as0 + c[0][ni][3] * as1;
            s[2] += c[1][ni][0] * as0 + c[1][ni][1] * as1;
            s[3] += c[1][ni][2] * as0 + c[1][ni][3] * as1;
            d[0] += c[0][ni][0] * ad0 + c[0][ni][1] * ad1;
            d[1] += c[0][ni][2] * ad0 + c[0][ni][3] * ad1;
            d[2] += c[1][ni][0] * ad0 + c[1][ni][1] * ad1;
            d[3] += c[1][ni][2] * ad0 + c[1][ni][3] * ad1;
        }
#pragma unroll
        for (int off = 1; off <= 2; off <<= 1) {
#pragma unroll
            for (int j = 0; j < 4; j++) {
                s[j] += __shfl_xor_sync(FULLMASK, s[j], off);
                d[j] += __shfl_xor_sync(FULLMASK, d[j], off);
            }
        }
        if (tg == 0) {
            int rbase = bm + m0 + g;
#pragma unroll
            for (int j = 0; j < 4; j++) {
                int r = rbase + ((j & 1) ? 8 : 0) + ((j >> 1) ? 16 : 0);
                if (r < N_NODESK) {
                    g_as1[r * 8 + hidx] = s[j];
                    g_ad1[r * 8 + hidx] = d[j];
                }
            }
        }
    }
}

__device__ __forceinline__ float lrelu02(float x) { return x > 0.f ? x : 0.2f * x; }
__device__ __forceinline__ float eluf(float x)    { return x > 0.f ? x : expm1f(x); }

// accumulate 4 fp16 channels (one uint2 = 2 half2) into fp32 acc with weight w
__device__ __forceinline__ void acc_h4(float4& acc, uint2 p, float w) {
    float2 a = __half22float2(*(__half2*)&p.x);
    float2 b = __half22float2(*(__half2*)&p.y);
    acc.x += w * a.x; acc.y += w * a.y;
    acc.z += w * b.x; acc.w += w * b.y;
}

// ---------------- layer-1 aggregation (quad-edge, exp-dedup, fp16 gather) + layer-2 fuse --
__global__ __launch_bounds__(256) void agg1_kernel(const float* __restrict__ b1,
                                                   const float* __restrict__ W2,
                                                   const float* __restrict__ a2s,
                                                   const float* __restrict__ a2d) {
    int warp = (blockIdx.x * blockDim.x + threadIdx.x) >> 5;
    int lane = threadIdx.x & 31;
    if (warp >= N_NODESK) return;
    const int n = warp;
    const int hA = lane >> 3;
    const int hB = 4 + hA;
    const int l7 = lane & 7;
    const int grp = lane >> 3;
    const float ad8 = g_ad1[n * 8 + l7];

    float4 accA = make_float4(0.f, 0.f, 0.f, 0.f);
    float4 accB = make_float4(0.f, 0.f, 0.f, 0.f);
    float denA = 0.f, denB = 0.f;

    const int beg = g_rowptr[n], end = g_rowptr[n + 1];

    {   // self loop
        float w = __expf(lrelu02(g_as1[n * 8 + l7] + ad8));
        float wA = __shfl_sync(FULLMASK, w, hA);
        float wB = __shfl_sync(FULLMASK, w, hB);
        const uint2* row = (const uint2*)(g_h1h + (size_t)n * 128);
        acc_h4(accA, row[lane], wA);
        acc_h4(accB, row[32 + lane], wB);
        denA += wA; denB += wB;
    }

    int e = beg;
    for (; e + 4 <= end; e += 4) {
        int ss = g_col[e + grp];
        float w = __expf(lrelu02(g_as1[ss * 8 + l7] + ad8));
#pragma unroll
        for (int j = 0; j < 4; ++j) {
            int  sj = __shfl_sync(FULLMASK, ss, j * 8);
            float wA = __shfl_sync(FULLMASK, w, j * 8 + hA);
            float wB = __shfl_sync(FULLMASK, w, j * 8 + hB);
            const uint2* row = (const uint2*)(g_h1h + (size_t)sj * 128);
            acc_h4(accA, row[lane], wA);
            acc_h4(accB, row[32 + lane], wB);
            denA += wA; denB += wB;
        }
    }
    for (; e < end; ++e) {
        int s = g_col[e];
        float w = __expf(lrelu02(g_as1[s * 8 + l7] + ad8));
        float wA = __shfl_sync(FULLMASK, w, hA);
        float wB = __shfl_sync(FULLMASK, w, hB);
        const uint2* row = (const uint2*)(g_h1h + (size_t)s * 128);
        acc_h4(accA, row[lane], wA);
        acc_h4(accB, row[32 + lane], wB);
        denA += wA; denB += wB;
    }

    float rA = 1.f / denA, rB = 1.f / denB;
    const float4 bA = *(const float4*)(b1 + 4 * lane);
    const float4 bB = *(const float4*)(b1 + 128 + 4 * lane);
    float4 oA, oB;
    oA.x = eluf(accA.x * rA + bA.x); oA.y = eluf(accA.y * rA + bA.y);
    oA.z = eluf(accA.z * rA + bA.z); oA.w = eluf(accA.w * rA + bA.w);
    oB.x = eluf(accB.x * rB + bB.x); oB.y = eluf(accB.y * rB + bB.y);
    oB.z = eluf(accB.z * rB + bB.z); oB.w = eluf(accB.w * rB + bB.w);

    int cA = 4 * lane, cB = 128 + 4 * lane;
    float acc0 = oA.x * W2[(cA + 0) * 2] + oA.y * W2[(cA + 1) * 2]
               + oA.z * W2[(cA + 2) * 2] + oA.w * W2[(cA + 3) * 2]
               + oB.x * W2[(cB + 0) * 2] + oB.y * W2[(cB + 1) * 2]
               + oB.z * W2[(cB + 2) * 2] + oB.w * W2[(cB + 3) * 2];
    float acc1 = oA.x * W2[(cA + 0) * 2 + 1] + oA.y * W2[(cA + 1) * 2 + 1]
               + oA.z * W2[(cA + 2) * 2 + 1] + oA.w * W2[(cA + 3) * 2 + 1]
               + oB.x * W2[(cB + 0) * 2 + 1] + oB.y * W2[(cB + 1) * 2 + 1]
               + oB.z * W2[(cB + 2) * 2 + 1] + oB.w * W2[(cB + 3) * 2 + 1];
#pragma unroll
    for (int o = 16; o; o >>= 1) {
        acc0 += __shfl_xor_sync(FULLMASK, acc0, o);
        acc1 += __shfl_xor_sync(FULLMASK, acc1, o);
    }
    if (lane == 0) {
        g_h2[n * 2 + 0] = acc0;
        g_h2[n * 2 + 1] = acc1;
        g_as2[n] = acc0 * a2s[0] + acc1 * a2s[1];
        g_ad2[n] = acc0 * a2d[0] + acc1 * a2d[1];
    }
}

// ---------------- layer-2 aggregation: warp per dst node (edge-parallel) ----------------
__global__ __launch_bounds__(256) void agg2_kernel(const float* __restrict__ b2,
                                                   float* __restrict__ out) {
    int warp = (blockIdx.x * blockDim.x + threadIdx.x) >> 5;
    int lane = threadIdx.x & 31;
    if (warp >= N_NODESK) return;
    const int n = warp;
    float adn = g_ad2[n];
    int beg = g_rowptr[n], end = g_rowptr[n + 1];
    float den = 0.f, o0 = 0.f, o1 = 0.f;
    for (int e = beg + lane; e < end; e += 32) {
        int s = g_col[e];
        float w = __expf(lrelu02(g_as2[s] + adn));
        den += w;
        o0 += w * g_h2[s * 2 + 0];
        o1 += w * g_h2[s * 2 + 1];
    }
    if (lane == 0) {
        float w = __expf(lrelu02(g_as2[n] + adn));
        den += w;
        o0 += w * g_h2[n * 2 + 0];
        o1 += w * g_h2[n * 2 + 1];
    }
#pragma unroll
    for (int o = 16; o; o >>= 1) {
        den += __shfl_xor_sync(FULLMASK, den, o);
        o0  += __shfl_xor_sync(FULLMASK, o0, o);
        o1  += __shfl_xor_sync(FULLMASK, o1, o);
    }
    if (lane == 0) {
        float r = 1.f / den;
        out[n * 2 + 0] = o0 * r + b2[0];
        out[n * 2 + 1] = o1 * r + b2[1];
    }
}

// ---------------- launch ----------------
extern "C" void kernel_launch(void* const* d_in, const int* in_sizes, int n_in,
                              void* d_out, int out_size) {
    const float* x    = (const float*)d_in[0];
    const int*   ei   = (const int*)d_in[1];
    const float* W1   = (const float*)d_in[3];
    const float* a1s  = (const float*)d_in[4];
    const float* a1d  = (const float*)d_in[5];
    const float* b1   = (const float*)d_in[6];
    const float* W2   = (const float*)d_in[7];
    const float* a2s  = (const float*)d_in[8];
    const float* a2d  = (const float*)d_in[9];
    const float* b2   = (const float*)d_in[10];
    float* out = (float*)d_out;

    const int* src = ei;
    const int* dst = ei + N_EDGESK;

    // sgemm kept as launch #4 (profiler captures the 4th launch)
    zero_cnt_kernel<<<(N_NODESK + 255) / 256, 256>>>();
    splitW1_kernel<<<(F_INK * C1K + 255) / 256, 256>>>(W1);
    hist_kernel<<<(N_EDGESK / 4 + 255) / 256, 256>>>(dst);
    sgemm_tc_kernel<<<dim3(C1K / 64, (N_NODESK + 127) / 128), 256>>>(x, a1s, a1d);
    blocksum_kernel<<<NBLK_SCAN, 256>>>();
    scanlocal_kernel<<<NBLK_SCAN, 256>>>();
    scatter_kernel<<<(N_EDGESK / 4 + 255) / 256, 256>>>(src, dst);

    agg1_kernel<<<(N_NODESK * 32 + 255) / 256, 256>>>(b1, W2, a2s, a2d);
    agg2_kernel<<<(N_NODESK * 32 + 255) / 256, 256>>>(b2, out);
}

// round 17
// speedup vs baseline: 1.1910x; 1.0186x over previous
#include <cuda_runtime.h>
#include <cuda_fp16.h>
#include <cstdint>
#include <math.h>

#define N_NODESK 50000
#define N_EDGESK 800000
#define F_INK    128
#define C1K      256     // HEADS*HID
#define HEADSK   8
#define NBLK_SCAN 196    // ceil(50000/256)
#define FULLMASK 0xffffffffu

// ---------------- scratch (device globals: allocation-free contract) ----------------
__device__ __half2 g_h1h[N_NODESK * 128];  // h1 in fp16 (half2 pairs), 25.6 MB
__device__ __half  g_W1th[C1K * F_INK];    // W1^T hi-half, [n][k]
__device__ __half  g_W1tl[C1K * F_INK];    // W1^T lo-half, [n][k]
__device__ float g_as1[N_NODESK * HEADSK];
__device__ float g_ad1[N_NODESK * HEADSK];
__device__ float g_h2[N_NODESK * 2];
__device__ float g_as2[N_NODESK];
__device__ float g_ad2[N_NODESK];
__device__ int   g_cnt[N_NODESK];
__device__ int   g_rowptr[N_NODESK + 1];
__device__ int   g_cursor[N_NODESK];
__device__ int   g_col[N_EDGESK];          // src ids grouped by dst
__device__ int   g_bsum[NBLK_SCAN];

// ---------------- CSR build ----------------
__global__ void zero_cnt_kernel() {
    int i = blockIdx.x * blockDim.x + threadIdx.x;
    if (i < N_NODESK) g_cnt[i] = 0;
}

// one-time W1 transpose + fp16 hi/lo split: g_W1t*[n][k]
__global__ void splitW1_kernel(const float* __restrict__ W1) {
    int t = blockIdx.x * blockDim.x + threadIdx.x;
    if (t < F_INK * C1K) {
        int k = t & (F_INK - 1);
        int n = t >> 7;
        float v = W1[(size_t)k * C1K + n];
        __half h = __float2half_rn(v);
        float l = v - __half2float(h);
        g_W1th[n * F_INK + k] = h;
        g_W1tl[n * F_INK + k] = __float2half_rn(l);
    }
}

// 4 edges per thread, int4 loads -> 4 independent atomics (MLP=4)
__global__ void hist_kernel(const int* __restrict__ dst) {
    int t = blockIdx.x * blockDim.x + threadIdx.x;
    if (t < N_EDGESK / 4) {
        int4 d = ((const int4*)dst)[t];
        atomicAdd(&g_cnt[d.x], 1);
        atomicAdd(&g_cnt[d.y], 1);
        atomicAdd(&g_cnt[d.z], 1);
        atomicAdd(&g_cnt[d.w], 1);
    }
}

__global__ void blocksum_kernel() {
    int i = blockIdx.x * 256 + threadIdx.x;
    int v = (i < N_NODESK) ? g_cnt[i] : 0;
    __shared__ int ws[8];
    int lane = threadIdx.x & 31, w = threadIdx.x >> 5;
#pragma unroll
    for (int o = 16; o; o >>= 1) v += __shfl_xor_sync(FULLMASK, v, o);
    if (lane == 0) ws[w] = v;
    __syncthreads();
    if (threadIdx.x == 0) {
        int s = 0;
#pragma unroll
        for (int k = 0; k < 8; k++) s += ws[k];
        g_bsum[blockIdx.x] = s;
    }
}

// local scan with top-level prefix over g_bsum computed in-block
__global__ void scanlocal_kernel() {
    __shared__ int sh[256];
    __shared__ int wsum[8];
    int part = 0;
    for (int j = threadIdx.x; j < blockIdx.x; j += 256) part += g_bsum[j];
    {
        int lane = threadIdx.x & 31, w = threadIdx.x >> 5;
#pragma unroll
        for (int o = 16; o; o >>= 1) part += __shfl_xor_sync(FULLMASK, part, o);
        if (lane == 0) wsum[w] = part;
    }
    __syncthreads();
    int base = wsum[0] + wsum[1] + wsum[2] + wsum[3] + wsum[4] + wsum[5] + wsum[6] + wsum[7];

    int i = blockIdx.x * 256 + threadIdx.x;
    int v = (i < N_NODESK) ? g_cnt[i] : 0;
    sh[threadIdx.x] = v;
    __syncthreads();
    for (int off = 1; off < 256; off <<= 1) {
        int t = (threadIdx.x >= off) ? sh[threadIdx.x - off] : 0;
        __syncthreads();
        sh[threadIdx.x] += t;
        __syncthreads();
    }
    int incl = sh[threadIdx.x];
    if (i < N_NODESK) {
        int excl = base + incl - v;
        g_rowptr[i] = excl;
        g_cursor[i] = excl;
        if (i == N_NODESK - 1) g_rowptr[N_NODESK] = base + incl;
    }
}

__global__ void scatter_kernel(const int* __restrict__ src, const int* __restrict__ dst) {
    int t = blockIdx.x * blockDim.x + threadIdx.x;
    if (t < N_EDGESK / 4) {
        int4 s = ((const int4*)src)[t];
        int4 d = ((const int4*)dst)[t];
        int p0 = atomicAdd(&g_cursor[d.x], 1);
        int p1 = atomicAdd(&g_cursor[d.y], 1);
        int p2 = atomicAdd(&g_cursor[d.z], 1);
        int p3 = atomicAdd(&g_cursor[d.w], 1);
        g_col[p0] = s.x;
        g_col[p1] = s.y;
        g_col[p2] = s.z;
        g_col[p3] = s.w;
    }
}

// ---------------- tensor-core SGEMM (3-term fp16-split, ldmatrix frags) + fused alpha1 ----
// h1 = x @ W1 as Ah*Bh + Ah*Bl + Al*Bh with fp16 mma (exact 11x11-bit products, fp32 acc).
// Fragments loaded via ldmatrix.m8n8.x4 — 8 LDSM per k16 step vs 32 scalar LDS.
// Smem row stride 20 words makes the 8 LDSM row-fetches bank-conflict-free.

__device__ __forceinline__ void h2split(float a, float b, unsigned int& hi, unsigned int& lo) {
    __half ha = __float2half_rn(a), hb = __float2half_rn(b);
    __half la = __float2half_rn(a - __half2float(ha));
    __half lb = __float2half_rn(b - __half2float(hb));
    hi = ((unsigned int)__half_as_ushort(hb) << 16) | __half_as_ushort(ha);
    lo = ((unsigned int)__half_as_ushort(lb) << 16) | __half_as_ushort(la);
}

__device__ __forceinline__ void mma_f16(float* c, const unsigned int* a, const unsigned int* b) {
    asm volatile(
        "mma.sync.aligned.m16n8k16.row.col.f32.f16.f16.f32 "
        "{%0,%1,%2,%3}, {%4,%5,%6,%7}, {%8,%9}, {%0,%1,%2,%3};"
        : "+f"(c[0]), "+f"(c[1]), "+f"(c[2]), "+f"(c[3])
        : "r"(a[0]), "r"(a[1]), "r"(a[2]), "r"(a[3]), "r"(b[0]), "r"(b[1]));
}

__device__ __forceinline__ void ldsm_x4(unsigned int* r, unsigned int addr) {
    asm volatile(
        "ldmatrix.sync.aligned.m8n8.x4.shared.b16 {%0,%1,%2,%3}, [%4];"
        : "=r"(r[0]), "=r"(r[1]), "=r"(r[2]), "=r"(r[3]) : "r"(addr));
}

__global__ __launch_bounds__(256, 2) void sgemm_tc_kernel(const float* __restrict__ A,
                                                          const float* __restrict__ a1s,
                                                          const float* __restrict__ a1d) {
    // payload: 16 half2 words (=32 k halves) per row; stride 20 words
    __shared__ unsigned int sAh[128][20], sAl[128][20];
    __shared__ unsigned int sBh[64][20],  sBl[64][20];

    const int tid  = threadIdx.x;
    const int lane = tid & 31;
    const int wid  = tid >> 5;
    const int g    = lane >> 2;       // 0..7
    const int tg   = lane & 3;        // 0..3
    const int m0   = (wid & 3) * 32;
    const int n0   = (wid >> 2) * 32;
    const int bm   = blockIdx.y * 128;
    const int bn   = blockIdx.x * 64;

    const unsigned int aAh = (unsigned int)__cvta_generic_to_shared(&sAh[0][0]);
    const unsigned int aAl = (unsigned int)__cvta_generic_to_shared(&sAl[0][0]);
    const unsigned int aBh = (unsigned int)__cvta_generic_to_shared(&sBh[0][0]);
    const unsigned int aBl = (unsigned int)__cvta_generic_to_shared(&sBl[0][0]);

    float c[2][4][4];
#pragma unroll
    for (int mi = 0; mi < 2; mi++)
#pragma unroll
        for (int ni = 0; ni < 4; ni++)
#pragma unroll
            for (int q = 0; q < 4; q++) c[mi][ni][q] = 0.f;

    for (int kt = 0; kt < F_INK; kt += 32) {
        // A tile: 128 rows x 32 k floats; 4 float4 per thread; split to fp16 hi/lo
#pragma unroll
        for (int i = 0; i < 4; i++) {
            int idx = tid + i * 256;
            int row = idx >> 3, kq = idx & 7;
            float4 v = make_float4(0.f, 0.f, 0.f, 0.f);
            int grow = bm + row;
            if (grow < N_NODESK)
                v = *(const float4*)(A + (size_t)grow * F_INK + kt + kq * 4);
            unsigned int h0, l0, h1, l1;
            h2split(v.x, v.y, h0, l0);
            h2split(v.z, v.w, h1, l1);
            sAh[row][kq * 2 + 0] = h0;
            sAh[row][kq * 2 + 1] = h1;
            sAl[row][kq * 2 + 0] = l0;
            sAl[row][kq * 2 + 1] = l1;
        }
        // B tile from pre-split W1^T [n][k] halves: 64 rows x 32 k; uint4 per thread
        {
            int row = tid >> 2, kq = tid & 3;
            const uint4 vh = *(const uint4*)(g_W1th + (size_t)(bn + row) * F_INK + kt + kq * 8);
            const uint4 vl = *(const uint4*)(g_W1tl + (size_t)(bn + row) * F_INK + kt + kq * 8);
            sBh[row][kq * 4 + 0] = vh.x; sBh[row][kq * 4 + 1] = vh.y;
            sBh[row][kq * 4 + 2] = vh.z; sBh[row][kq * 4 + 3] = vh.w;
            sBl[row][kq * 4 + 0] = vl.x; sBl[row][kq * 4 + 1] = vl.y;
            sBl[row][kq * 4 + 2] = vl.z; sBl[row][kq * 4 + 3] = vl.w;
        }
        __syncthreads();
#pragma unroll
        for (int s = 0; s < 2; ++s) {        // two k16 steps per stage
            const int kk = s * 8;
            const int mat = lane >> 3, r8 = lane & 7;
            unsigned int ah[2][4], al[2][4], bh[4][2], bl[4][2];
            // A frags: x4 = (m0,k0),(m8,k0),(m0,k8),(m8,k8)
#pragma unroll
            for (int mi = 0; mi < 2; mi++) {
                int arow = m0 + mi * 16 + ((mat & 1) << 3) + r8;
                int awrd = kk + ((mat >> 1) << 2);
                unsigned int off = (unsigned int)(arow * 20 + awrd) * 4u;
                ldsm_x4(ah[mi], aAh + off);
                ldsm_x4(al[mi], aAl + off);
            }
            // B frags: x4 = (n0,k0),(n0,k8),(n8,k0),(n8,k8) -> two ni at once
#pragma unroll
            for (int p = 0; p < 2; p++) {
                int nrow = n0 + p * 16 + ((mat >> 1) << 3) + r8;
                int wrd  = kk + ((mat & 1) << 2);
                unsigned int off = (unsigned int)(nrow * 20 + wrd) * 4u;
                unsigned int t0[4], t1[4];
                ldsm_x4(t0, aBh + off);
                ldsm_x4(t1, aBl + off);
                bh[2 * p][0] = t0[0]; bh[2 * p][1] = t0[1];
                bh[2 * p + 1][0] = t0[2]; bh[2 * p + 1][1] = t0[3];
                bl[2 * p][0] = t1[0]; bl[2 * p][1] = t1[1];
                bl[2 * p + 1][0] = t1[2]; bl[2 * p + 1][1] = t1[3];
            }
#pragma unroll
            for (int mi = 0; mi < 2; mi++)
#pragma unroll
                for (int ni = 0; ni < 4; ni++) {
                    mma_f16(c[mi][ni], ah[mi], bh[ni]);
                    mma_f16(c[mi][ni], ah[mi], bl[ni]);
                    mma_f16(c[mi][ni], al[mi], bh[ni]);
                }
        }
        __syncthreads();
    }

    // store C tile as fp16 (half2 per channel pair)
#pragma unroll
    for (int mi = 0; mi < 2; mi++)
#pragma unroll
        for (int ni = 0; ni < 4; ni++) {
            int r = bm + m0 + mi * 16 + g;
            int col = bn + n0 + ni * 8 + tg * 2;   // even
            if (r < N_NODESK)
                g_h1h[(size_t)r * 128 + (col >> 1)] =
                    __floats2half2_rn(c[mi][ni][0], c[mi][ni][1]);
            if (r + 8 < N_NODESK)
                g_h1h[(size_t)(r + 8) * 128 + (col >> 1)] =
                    __floats2half2_rn(c[mi][ni][2], c[mi][ni][3]);
        }

    // fused alpha1 from fp32 accumulators: this warp's 32-col slab == one head
    {
        int hidx = (bn >> 5) + (wid >> 2);
        float s[4] = {0.f, 0.f, 0.f, 0.f};
        float d[4] = {0.f, 0.f, 0.f, 0.f};
#pragma unroll
        for (int ni = 0; ni < 4; ni++) {
            int lc = ni * 8 + tg * 2;
            float as0 = a1s[hidx * 32 + lc], as1 = a1s[hidx * 32 + lc + 1];
            float ad0 = a1d[hidx * 32 + lc], ad1 = a1d[hidx * 32 + lc + 1];
            s[0] += c[0][ni][0] * as0 + c[0][ni][1] * as1;
            s[1] += c[0][ni][2] * as0 + c[0][ni][3] * as1;
            s[2] += c[1][ni][0] * as0 + c[1][ni][1] * as1;
            s[3] += c[1][ni][2] * as0 + c[1][ni][3] * as1;
            d[0] += c[0][ni][0] * ad0 + c[0][ni][1] * ad1;
            d[1] += c[0][ni][2] * ad0 + c[0][ni][3] * ad1;
            d[2] += c[1][ni][0] * ad0 + c[1][ni][1] * ad1;
            d[3] += c[1][ni][2] * ad0 + c[1][ni][3] * ad1;
        }
#pragma unroll
        for (int off = 1; off <= 2; off <<= 1) {
#pragma unroll
            for (int j = 0; j < 4; j++) {
                s[j] += __shfl_xor_sync(FULLMASK, s[j], off);
                d[j] += __shfl_xor_sync(FULLMASK, d[j], off);
            }
        }
        if (tg == 0) {
            int rbase = bm + m0 + g;
#pragma unroll
            for (int j = 0; j < 4; j++) {
                int r = rbase + ((j & 1) ? 8 : 0) + ((j >> 1) ? 16 : 0);
                if (r < N_NODESK) {
                    g_as1[r * 8 + hidx] = s[j];
                    g_ad1[r * 8 + hidx] = d[j];
                }
            }
        }
    }
}

__device__ __forceinline__ float lrelu02(float x) { return x > 0.f ? x : 0.2f * x; }
__device__ __forceinline__ float eluf(float x)    { return x > 0.f ? x : expm1f(x); }

// accumulate 4 fp16 channels (one uint2 = 2 half2) into fp32 acc with weight w
__device__ __forceinline__ void acc_h4(float4& acc, uint2 p, float w) {
    float2 a = __half22float2(*(__half2*)&p.x);
    float2 b = __half22float2(*(__half2*)&p.y);
    acc.x += w * a.x; acc.y += w * a.y;
    acc.z += w * b.x; acc.w += w * b.y;
}

// ---------------- layer-1 aggregation (quad-edge, exp-dedup, fp16 gather) + layer-2 fuse --
__global__ __launch_bounds__(256) void agg1_kernel(const float* __restrict__ b1,
                                                   const float* __restrict__ W2,
                                                   const float* __restrict__ a2s,
                                                   const float* __restrict__ a2d) {
    int warp = (blockIdx.x * blockDim.x + threadIdx.x) >> 5;
    int lane = threadIdx.x & 31;
    if (warp >= N_NODESK) return;
    const int n = warp;
    const int hA = lane >> 3;
    const int hB = 4 + hA;
    const int l7 = lane & 7;
    const int grp = lane >> 3;
    const float ad8 = g_ad1[n * 8 + l7];

    float4 accA = make_float4(0.f, 0.f, 0.f, 0.f);
    float4 accB = make_float4(0.f, 0.f, 0.f, 0.f);
    float denA = 0.f, denB = 0.f;

    const int beg = g_rowptr[n], end = g_rowptr[n + 1];

    {   // self loop
        float w = __expf(lrelu02(g_as1[n * 8 + l7] + ad8));
        float wA = __shfl_sync(FULLMASK, w, hA);
        float wB = __shfl_sync(FULLMASK, w, hB);
        const uint2* row = (const uint2*)(g_h1h + (size_t)n * 128);
        acc_h4(accA, row[lane], wA);
        acc_h4(accB, row[32 + lane], wB);
        denA += wA; denB += wB;
    }

    int e = beg;
    for (; e + 4 <= end; e += 4) {
        int ss = g_col[e + grp];
        float w = __expf(lrelu02(g_as1[ss * 8 + l7] + ad8));
#pragma unroll
        for (int j = 0; j < 4; ++j) {
            int  sj = __shfl_sync(FULLMASK, ss, j * 8);
            float wA = __shfl_sync(FULLMASK, w, j * 8 + hA);
            float wB = __shfl_sync(FULLMASK, w, j * 8 + hB);
            const uint2* row = (const uint2*)(g_h1h + (size_t)sj * 128);
            acc_h4(accA, row[lane], wA);
            acc_h4(accB, row[32 + lane], wB);
            denA += wA; denB += wB;
        }
    }
    for (; e < end; ++e) {
        int s = g_col[e];
        float w = __expf(lrelu02(g_as1[s * 8 + l7] + ad8));
        float wA = __shfl_sync(FULLMASK, w, hA);
        float wB = __shfl_sync(FULLMASK, w, hB);
        const uint2* row = (const uint2*)(g_h1h + (size_t)s * 128);
        acc_h4(accA, row[lane], wA);
        acc_h4(accB, row[32 + lane], wB);
        denA += wA; denB += wB;
    }

    float rA = 1.f / denA, rB = 1.f / denB;
    const float4 bA = *(const float4*)(b1 + 4 * lane);
    const float4 bB = *(const float4*)(b1 + 128 + 4 * lane);
    float4 oA, oB;
    oA.x = eluf(accA.x * rA + bA.x); oA.y = eluf(accA.y * rA + bA.y);
    oA.z = eluf(accA.z * rA + bA.z); oA.w = eluf(accA.w * rA + bA.w);
    oB.x = eluf(accB.x * rB + bB.x); oB.y = eluf(accB.y * rB + bB.y);
    oB.z = eluf(accB.z * rB + bB.z); oB.w = eluf(accB.w * rB + bB.w);

    int cA = 4 * lane, cB = 128 + 4 * lane;
    float acc0 = oA.x * W2[(cA + 0) * 2] + oA.y * W2[(cA + 1) * 2]
               + oA.z * W2[(cA + 2) * 2] + oA.w * W2[(cA + 3) * 2]
               + oB.x * W2[(cB + 0) * 2] + oB.y * W2[(cB + 1) * 2]
               + oB.z * W2[(cB + 2) * 2] + oB.w * W2[(cB + 3) * 2];
    float acc1 = oA.x * W2[(cA + 0) * 2 + 1] + oA.y * W2[(cA + 1) * 2 + 1]
               + oA.z * W2[(cA + 2) * 2 + 1] + oA.w * W2[(cA + 3) * 2 + 1]
               + oB.x * W2[(cB + 0) * 2 + 1] + oB.y * W2[(cB + 1) * 2 + 1]
               + oB.z * W2[(cB + 2) * 2 + 1] + oB.w * W2[(cB + 3) * 2 + 1];
#pragma unroll
    for (int o = 16; o; o >>= 1) {
        acc0 += __shfl_xor_sync(FULLMASK, acc0, o);
        acc1 += __shfl_xor_sync(FULLMASK, acc1, o);
    }
    if (lane == 0) {
        g_h2[n * 2 + 0] = acc0;
        g_h2[n * 2 + 1] = acc1;
        g_as2[n] = acc0 * a2s[0] + acc1 * a2s[1];
        g_ad2[n] = acc0 * a2d[0] + acc1 * a2d[1];
    }
}

// ---------------- layer-2 aggregation: warp per dst node (edge-parallel) ----------------
__global__ __launch_bounds__(256) void agg2_kernel(const float* __restrict__ b2,
                                                   float* __restrict__ out) {
    int warp = (blockIdx.x * blockDim.x + threadIdx.x) >> 5;
    int lane = threadIdx.x & 31;
    if (warp >= N_NODESK) return;
    const int n = warp;
    float adn = g_ad2[n];
    int beg = g_rowptr[n], end = g_rowptr[n + 1];
    float den = 0.f, o0 = 0.f, o1 = 0.f;
    for (int e = beg + lane; e < end; e += 32) {
        int s = g_col[e];
        float w = __expf(lrelu02(g_as2[s] + adn));
        den += w;
        o0 += w * g_h2[s * 2 + 0];
        o1 += w * g_h2[s * 2 + 1];
    }
    if (lane == 0) {
        float w = __expf(lrelu02(g_as2[n] + adn));
        den += w;
        o0 += w * g_h2[n * 2 + 0];
        o1 += w * g_h2[n * 2 + 1];
    }
#pragma unroll
    for (int o = 16; o; o >>= 1) {
        den += __shfl_xor_sync(FULLMASK, den, o);
        o0  += __shfl_xor_sync(FULLMASK, o0, o);
        o1  += __shfl_xor_sync(FULLMASK, o1, o);
    }
    if (lane == 0) {
        float r = 1.f / den;
        out[n * 2 + 0] = o0 * r + b2[0];
        out[n * 2 + 1] = o1 * r + b2[1];
    }
}

// ---------------- launch ----------------
extern "C" void kernel_launch(void* const* d_in, const int* in_sizes, int n_in,
                              void* d_out, int out_size) {
    const float* x    = (const float*)d_in[0];
    const int*   ei   = (const int*)d_in[1];
    const float* W1   = (const float*)d_in[3];
    const float* a1s  = (const float*)d_in[4];
    const float* a1d  = (const float*)d_in[5];
    const float* b1   = (const float*)d_in[6];
    const float* W2   = (const float*)d_in[7];
    const float* a2s  = (const float*)d_in[8];
    const float* a2d  = (const float*)d_in[9];
    const float* b2   = (const float*)d_in[10];
    float* out = (float*)d_out;

    const int* src = ei;
    const int* dst = ei + N_EDGESK;

    // sgemm kept as launch #4 (profiler captures the 4th launch)
    zero_cnt_kernel<<<(N_NODESK + 255) / 256, 256>>>();
    splitW1_kernel<<<(F_INK * C1K + 255) / 256, 256>>>(W1);
    hist_kernel<<<(N_EDGESK / 4 + 255) / 256, 256>>>(dst);
    sgemm_tc_kernel<<<dim3(C1K / 64, (N_NODESK + 127) / 128), 256>>>(x, a1s, a1d);
    blocksum_kernel<<<NBLK_SCAN, 256>>>();
    scanlocal_kernel<<<NBLK_SCAN, 256>>>();
    scatter_kernel<<<(N_EDGESK / 4 + 255) / 256, 256>>>(src, dst);

    agg1_kernel<<<(N_NODESK * 32 + 255) / 256, 256>>>(b1, W2, a2s, a2d);
    agg2_kernel<<<(N_NODESK * 32 + 255) / 256, 256>>>(b2, out);
}